// round 12
// baseline (speedup 1.0000x reference)
#include <cuda_runtime.h>
#include <cuda_fp16.h>
#include <math.h>

// Problem constants (fixed shapes)
#define B 4
#define C 128
#define H 256
#define W 256
#define HW 65536
#define NH 8
#define DH 16
#define KS 7
#define GROUPS 8
#define CPG 16
#define EPS 1e-5f

// ---------------- scratch (device globals) ----------------
__device__ float    g_psum[B * C];
__device__ float    g_psum2[B * C];
__device__ float    g_scale[B * C];
__device__ float    g_shift[B * C];
// qkv packed fp16x2: [qkvi(3)][b(4)][h(8)][ij(65536)][dw(8)]
__device__ unsigned g_qkv_w[(size_t)3 * B * NH * HW * (DH / 2)];

// ---------------- helpers ----------------
__device__ __forceinline__ unsigned packh(float a, float b) {
    __half2 t = __floats2half2_rn(a, b);
    return *reinterpret_cast<unsigned*>(&t);
}
__device__ __forceinline__ void mma_f16(float* c,
                                        unsigned a0, unsigned a1, unsigned a2, unsigned a3,
                                        unsigned b0, unsigned b1) {
    asm volatile(
        "mma.sync.aligned.m16n8k16.row.col.f32.f16.f16.f32 "
        "{%0,%1,%2,%3}, {%4,%5,%6,%7}, {%8,%9}, {%0,%1,%2,%3};\n"
        : "+f"(c[0]), "+f"(c[1]), "+f"(c[2]), "+f"(c[3])
        : "r"(a0), "r"(a1), "r"(a2), "r"(a3), "r"(b0), "r"(b1));
}
// f16-accumulator MMA: D = 2 packed half2 regs
__device__ __forceinline__ void mma_f16acc(unsigned* c,
                                           unsigned a0, unsigned a1, unsigned a2, unsigned a3,
                                           unsigned b0, unsigned b1) {
    asm volatile(
        "mma.sync.aligned.m16n8k16.row.col.f16.f16.f16.f16 "
        "{%0,%1}, {%2,%3,%4,%5}, {%6,%7}, {%0,%1};\n"
        : "+r"(c[0]), "+r"(c[1])
        : "r"(a0), "r"(a1), "r"(a2), "r"(a3), "r"(b0), "r"(b1));
}
#define EXP_SCALE 0.36067376f   // 0.25 * log2(e)
__device__ __forceinline__ unsigned exph2p(unsigned p, unsigned sc2, unsigned bias) {
    unsigned r;
    asm("fma.rn.f16x2 %0, %1, %2, %3;" : "=r"(r) : "r"(p), "r"(sc2), "r"(bias));
    __half2 e = h2exp2(*reinterpret_cast<__half2*>(&r));
    return *reinterpret_cast<unsigned*>(&e);
}
__device__ __forceinline__ unsigned hadd2u(unsigned a, unsigned b) {
    __half2 r = __hadd2(*reinterpret_cast<__half2*>(&a), *reinterpret_cast<__half2*>(&b));
    return *reinterpret_cast<unsigned*>(&r);
}

// ---------------- kernel 1: GN statistics ----------------
__global__ __launch_bounds__(256) void gn_stats_kernel(const float* __restrict__ x) {
    const float4* p = (const float4*)(x + (size_t)blockIdx.x * HW);
    int tid = threadIdx.x;
    float s = 0.f, s2 = 0.f;
    for (int idx = tid; idx < HW / 4; idx += 256) {
        float4 v = p[idx];
        s  += v.x + v.y + v.z + v.w;
        s2 += v.x * v.x + v.y * v.y + v.z * v.z + v.w * v.w;
    }
    __shared__ float sh[256];
    sh[tid] = s; __syncthreads();
    for (int o = 128; o > 0; o >>= 1) { if (tid < o) sh[tid] += sh[tid + o]; __syncthreads(); }
    float bs = sh[0];
    __syncthreads();
    sh[tid] = s2; __syncthreads();
    for (int o = 128; o > 0; o >>= 1) { if (tid < o) sh[tid] += sh[tid + o]; __syncthreads(); }
    if (tid == 0) { g_psum[blockIdx.x] = bs; g_psum2[blockIdx.x] = sh[0]; }
}

// ---------------- kernel 2: finalize GN scale/shift ----------------
__global__ void gn_finalize_kernel(const float* __restrict__ gn_w, const float* __restrict__ gn_b) {
    int idx = blockIdx.x * 128 + threadIdx.x;
    if (idx >= B * C) return;
    int b = idx >> 7, c = idx & 127, g = c >> 4;
    int gbase = b * C + g * CPG;
    double s = 0.0, s2 = 0.0;
#pragma unroll
    for (int t = 0; t < CPG; t++) { s += (double)g_psum[gbase + t]; s2 += (double)g_psum2[gbase + t]; }
    const double N = (double)CPG * HW;
    double mu = s / N;
    double var = s2 / N - mu * mu;
    float rstd = (float)(1.0 / sqrt(var + (double)EPS));
    float sc = rstd * gn_w[c];
    g_scale[idx] = sc;
    g_shift[idx] = gn_b[c] - (float)mu * sc;
}

// ---------------- kernel 3: QKV GEMM (round-10 proven version) ----------------
#define QST 68    // smem word stride per row: 64 data words + 4 pad
extern __shared__ unsigned qsm[];   // As[128*QST] ++ Bs[128*QST] = 69632 B

__global__ __launch_bounds__(256) void qkv_gemm_kernel(const float* __restrict__ x,
                                                       const float* __restrict__ wq) {
    unsigned* As = qsm;
    unsigned* Bs = qsm + 128 * QST;

    int tid = threadIdx.x;
    int p0 = blockIdx.x * 128;
    int b  = p0 >> 16;
    int ij0 = p0 & (HW - 1);
    int warp = tid >> 5, lane = tid & 31;
    int wm = (warp >> 2) * 64, wn = (warp & 3) * 32;
    int g = lane >> 2, cq = lane & 3;

    // stage A once: 128 pixels x 64 words (128 channels), GN applied, fp16 packed
    const float* xb = x + (size_t)b * C * HW;
    int ap = tid & 127;
    int asw = (ap >> 3) & 3;
    for (int kw = tid >> 7; kw < 64; kw += 2) {
        int c = kw * 2;
        float v0 = fmaf(xb[(size_t)c * HW + ij0 + ap], g_scale[b * C + c], g_shift[b * C + c]);
        float v1 = fmaf(xb[(size_t)(c + 1) * HW + ij0 + ap], g_scale[b * C + c + 1], g_shift[b * C + c + 1]);
        As[ap * QST + (kw ^ asw)] = packh(v0, v1);
    }

    int bn = tid >> 5;
    int bkw = tid & 31;

    for (int qkvi = 0; qkvi < 3; qkvi++) {
        __syncthreads();
        for (int n = bn; n < 128; n += 8) {
            int sw = (n >> 3) & 3;
#pragma unroll
            for (int h2 = 0; h2 < 2; h2++) {
                int w = h2 * 32 + bkw;
                float2 f = *(const float2*)&wq[(size_t)(qkvi * 128 + n) * C + w * 2];
                Bs[n * QST + (w ^ sw)] = packh(f.x, f.y);
            }
        }
        __syncthreads();

        float acc[4][4][4];
#pragma unroll
        for (int mt = 0; mt < 4; mt++)
#pragma unroll
            for (int nt = 0; nt < 4; nt++)
#pragma unroll
                for (int t = 0; t < 4; t++) acc[mt][nt][t] = 0.f;

#pragma unroll
        for (int s = 0; s < 8; s++) {
            unsigned bf[4][2];
#pragma unroll
            for (int nt = 0; nt < 4; nt++) {
                int n = wn + nt * 8 + g;
                int sb = (n >> 3) & 3;
                bf[nt][0] = Bs[n * QST + ((s * 8 + cq) ^ sb)];
                bf[nt][1] = Bs[n * QST + ((s * 8 + 4 + cq) ^ sb)];
            }
#pragma unroll
            for (int mt = 0; mt < 4; mt++) {
                int m0 = wm + mt * 16 + g;
                int m1 = m0 + 8;
                int sa0 = (m0 >> 3) & 3, sa1 = (m1 >> 3) & 3;
                unsigned a0 = As[m0 * QST + ((s * 8 + cq) ^ sa0)];
                unsigned a1 = As[m1 * QST + ((s * 8 + cq) ^ sa1)];
                unsigned a2 = As[m0 * QST + ((s * 8 + 4 + cq) ^ sa0)];
                unsigned a3 = As[m1 * QST + ((s * 8 + 4 + cq) ^ sa1)];
#pragma unroll
                for (int nt = 0; nt < 4; nt++)
                    mma_f16(acc[mt][nt], a0, a1, a2, a3, bf[nt][0], bf[nt][1]);
            }
        }
        __syncthreads();

#pragma unroll
        for (int mt = 0; mt < 4; mt++) {
#pragma unroll
            for (int nt = 0; nt < 4; nt++) {
                int m0 = wm + mt * 16 + g, m1 = m0 + 8;
                int w = (wn + nt * 8) / 2 + cq;
                Bs[m0 * QST + w] = packh(acc[mt][nt][0], acc[mt][nt][1]);
                Bs[m1 * QST + w] = packh(acc[mt][nt][2], acc[mt][nt][3]);
            }
        }
        __syncthreads();

        uint4* gout = (uint4*)g_qkv_w;
        size_t tile_u4 = ((size_t)qkvi * 32 + b * 8) * ((size_t)HW * 2);
        for (int idx = tid; idx < 2048; idx += 256) {
            int h = idx >> 8;
            int rem = idx & 255;
            int ij = rem >> 1, half = rem & 1;
            uint4 val = *(uint4*)&Bs[ij * QST + h * 8 + half * 4];
            gout[tile_u4 + (size_t)h * HW * 2 + (size_t)(ij0 + ij) * 2 + half] = val;
        }
    }
}

// ---------------- kernel 4: FUSED neighborhood attention + proj + residual ----------------
// block: 8i x 16j pixel tile, loops all 8 heads; attention outputs land in the
// proj A smem buffer (qkv-style swizzled layout), then the proven MMA mainloop
// computes proj and the epilogue adds the residual. Grid (W/16, H/8, B).
#define TR 14
#define TCD 22
#define TCP 23
#define VST 8
#define KSMW (TR * TCP * VST + 32)
// dynamic smem: As[128*QST] ++ Bs[128*QST] ++ Ks[KSMW] ++ Vs[KSMW] = 90496 B

__global__ __launch_bounds__(256) void natten_proj_kernel(const float* __restrict__ x,
                                                          const float* __restrict__ wp,
                                                          const float* __restrict__ gamma,
                                                          float* __restrict__ out) {
    unsigned* As = qsm;
    unsigned* Bs = qsm + 128 * QST;
    unsigned* Ks = qsm + 2 * 128 * QST;
    unsigned* Vs = Ks + KSMW;

    int tid = threadIdx.x;
    int b = blockIdx.z;
    int i0 = blockIdx.y * 8, j0 = blockIdx.x * 16;
    int rb = i0 - 3; if (rb < 0) rb = 0; if (rb > H - TR) rb = H - TR;
    int cb = j0 - 3; if (cb < 0) cb = 0; if (cb > W - TCD) cb = W - TCD;

    int warp = tid >> 5, lane = tid & 31;

    // ---- stage proj weights into Bs (read after first head-loop sync) ----
    {
        int bn = tid >> 5, bkw = tid & 31;
        for (int n = bn; n < 128; n += 8) {
            int sw = (n >> 3) & 3;
#pragma unroll
            for (int h2 = 0; h2 < 2; h2++) {
                int w = h2 * 32 + bkw;
                float2 f = *(const float2*)&wp[(size_t)n * C + w * 2];
                Bs[n * QST + (w ^ sw)] = packh(f.x, f.y);
            }
        }
    }

    // ---- head-invariant attention setup (round-10 natten, verbatim) ----
    int wi = warp >> 1, wj = warp & 1;
    int qi0 = i0 + wi * 2, qj0 = j0 + wj * 8;
    int qrow = lane >> 2, qw = lane & 3;

    int si0 = qi0 - 3; if (si0 < 0) si0 = 0; if (si0 > H - 7) si0 = H - 7;
    int si1 = qi0 - 2; if (si1 < 0) si1 = 0; if (si1 > H - 7) si1 = H - 7;
    int wr0 = si0 - rb; if (wr0 > TR - 8) wr0 = TR - 8;
    int roff = (si0 - rb) - wr0;
    int r1 = roff + (si1 - si0);
    int sj0 = qj0 - 3; if (sj0 < 0) sj0 = 0; if (sj0 > W - 7) sj0 = W - 7;
    int wc0 = sj0 - cb; if (wc0 > TCD - 14) wc0 = TCD - 14;
    int oj = qj0 + qrow - 3; if (oj < 0) oj = 0; if (oj > W - 7) oj = W - 7;
    int cLo = oj - cb - wc0;

    bool v0m = (2 * qw)     >= roff;
    bool v1m = (2 * qw + 1) <= roff + 6;
    bool v2m = (2 * qw)     >= r1;
    bool v3m = (2 * qw + 1) <= r1 + 6;
    const unsigned NEG2 = 0xFC00FC00u;
    unsigned bias01 = (v0m ? 0u : 0xFC00u) | ((v1m ? 0u : 0xFC00u) << 16);
    unsigned bias23 = (v2m ? 0u : 0xFC00u) | ((v3m ? 0u : 0xFC00u) << 16);
    unsigned sc2 = packh(EXP_SCALE, EXP_SCALE);

    int kr = wr0 + qrow;
    const unsigned* kb = &Ks[(kr * TCP + wc0) * VST + ((kr & 7) << 2) + qw];
    int lm = lane & 7, mi = lane >> 3;
    int vr = wr0 + lm;
    unsigned vaddr = (unsigned)__cvta_generic_to_shared(
        &Vs[(vr * TCP + wc0 + (mi & 1)) * VST + ((vr & 7) << 2) + (mi >> 1) * 4]);

    // local pixel index (row group 0) for As writes
    int lp0 = wi * 32 + wj * 8 + qrow;
    int lp1 = lp0 + 16;
    int sw0 = (lp0 >> 3) & 3, sw1 = (lp1 >> 3) & 3;

    // ---- per-head attention -> As ----
    for (int h = 0; h < NH; h++) {
        size_t hb = ((size_t)b * NH + h) * ((size_t)HW * 8);
        const unsigned* qg = g_qkv_w + hb;
        const unsigned* kg = qg + (size_t)(B * NH) * HW * 8;
        const unsigned* vg = kg + (size_t)(B * NH) * HW * 8;

        __syncthreads();   // previous head's K/V readers done (h=0: Bs staging barrier)
        for (int idx = tid; idx < TR * TCD * 2; idx += 256) {
            int vec = idx >> 1, q = idx & 1;
            int r = vec / TCD, c = vec - r * TCD;
            size_t gw = ((size_t)(rb + r) * W + (cb + c)) * 8 + q * 4;
            int sw = (r * TCP + c) * VST + ((r & 7) << 2) + q * 4;
            *(uint4*)&Ks[sw] = *(const uint4*)&kg[gw];
            *(uint4*)&Vs[sw] = *(const uint4*)&vg[gw];
        }

        size_t qp0 = ((size_t)qi0 * W + qj0 + qrow) * 8;
        unsigned qa0 = qg[qp0 + qw];
        unsigned qa2 = qg[qp0 + qw + 4];
        unsigned qa1 = qg[qp0 + (size_t)W * 8 + qw];
        unsigned qa3 = qg[qp0 + (size_t)W * 8 + qw + 4];
        __syncthreads();   // K/V staged

        float o0[4] = {0.f, 0.f, 0.f, 0.f};
        float o1[4] = {0.f, 0.f, 0.f, 0.f};
        unsigned rs0 = 0u, rs1 = 0u;

#pragma unroll
        for (int kc = 0; kc < 7; kc++) {
            unsigned cE[2] = {0u, 0u};
            unsigned cO[2] = {0u, 0u};
            const unsigned* ke = kb + (2 * kc) * VST;
            mma_f16acc(cE, qa0, qa1, qa2, qa3, ke[0], ke[4]);
            mma_f16acc(cO, qa0, qa1, qa2, qa3, ke[VST], ke[VST + 4]);

            unsigned v0, v1, v2, v3;
            asm volatile("ldmatrix.sync.aligned.m8n8.x4.trans.shared.b16 {%0,%1,%2,%3}, [%4];"
                         : "=r"(v0), "=r"(v1), "=r"(v2), "=r"(v3)
                         : "r"(vaddr + 2 * kc * VST * 4));

            bool cvE = (unsigned)(2 * kc     - cLo) <= 6u;
            bool cvO = (unsigned)(2 * kc + 1 - cLo) <= 6u;
            unsigned bE01 = cvE ? bias01 : NEG2;
            unsigned bE23 = cvE ? bias23 : NEG2;
            unsigned bO01 = cvO ? bias01 : NEG2;
            unsigned bO23 = cvO ? bias23 : NEG2;
            unsigned aE01 = exph2p(cE[0], sc2, bE01);
            unsigned aE23 = exph2p(cE[1], sc2, bE23);
            unsigned aO01 = exph2p(cO[0], sc2, bO01);
            unsigned aO23 = exph2p(cO[1], sc2, bO23);
            rs0 = hadd2u(rs0, hadd2u(aE01, aO01));
            rs1 = hadd2u(rs1, hadd2u(aE23, aO23));

            mma_f16(o0, aE01, aE23, aO01, aO23, v0, v1);
            mma_f16(o1, aE01, aE23, aO01, aO23, v2, v3);
        }

        rs0 = hadd2u(rs0, __shfl_xor_sync(0xffffffffu, rs0, 1));
        rs0 = hadd2u(rs0, __shfl_xor_sync(0xffffffffu, rs0, 2));
        rs1 = hadd2u(rs1, __shfl_xor_sync(0xffffffffu, rs1, 1));
        rs1 = hadd2u(rs1, __shfl_xor_sync(0xffffffffu, rs1, 2));
        __half2 r0h = *reinterpret_cast<__half2*>(&rs0);
        __half2 r1h = *reinterpret_cast<__half2*>(&rs1);
        float inv0 = 1.f / (__low2float(r0h) + __high2float(r0h));
        float inv1 = 1.f / (__low2float(r1h) + __high2float(r1h));

        // write normalized outputs straight into proj-A smem (swizzled layout)
        As[lp0 * QST + ((h * 8 + qw)     ^ sw0)] = packh(o0[0] * inv0, o0[1] * inv0);
        As[lp0 * QST + ((h * 8 + 4 + qw) ^ sw0)] = packh(o1[0] * inv0, o1[1] * inv0);
        As[lp1 * QST + ((h * 8 + qw)     ^ sw1)] = packh(o0[2] * inv1, o0[3] * inv1);
        As[lp1 * QST + ((h * 8 + 4 + qw) ^ sw1)] = packh(o1[2] * inv1, o1[3] * inv1);
    }
    __syncthreads();   // As complete

    // ---- proj GEMM (proven 8-step mainloop) ----
    int wm = (warp >> 2) * 64, wn = (warp & 3) * 32;
    int g = lane >> 2, cq = lane & 3;

    float acc[4][4][4];
#pragma unroll
    for (int mt = 0; mt < 4; mt++)
#pragma unroll
        for (int nt = 0; nt < 4; nt++)
#pragma unroll
            for (int t = 0; t < 4; t++) acc[mt][nt][t] = 0.f;

#pragma unroll
    for (int s = 0; s < 8; s++) {
        unsigned bf[4][2];
#pragma unroll
        for (int nt = 0; nt < 4; nt++) {
            int n = wn + nt * 8 + g;
            int sb = (n >> 3) & 3;
            bf[nt][0] = Bs[n * QST + ((s * 8 + cq) ^ sb)];
            bf[nt][1] = Bs[n * QST + ((s * 8 + 4 + cq) ^ sb)];
        }
#pragma unroll
        for (int mt = 0; mt < 4; mt++) {
            int m0 = wm + mt * 16 + g;
            int m1 = m0 + 8;
            int sa0 = (m0 >> 3) & 3, sa1 = (m1 >> 3) & 3;
            unsigned a0 = As[m0 * QST + ((s * 8 + cq) ^ sa0)];
            unsigned a1 = As[m1 * QST + ((s * 8 + cq) ^ sa1)];
            unsigned a2 = As[m0 * QST + ((s * 8 + 4 + cq) ^ sa0)];
            unsigned a3 = As[m1 * QST + ((s * 8 + 4 + cq) ^ sa1)];
#pragma unroll
            for (int nt = 0; nt < 4; nt++)
                mma_f16(acc[mt][nt], a0, a1, a2, a3, bf[nt][0], bf[nt][1]);
        }
    }

    // ---- residual epilogue (2D pixel remap) ----
    float gm = gamma[0];
#pragma unroll
    for (int mt = 0; mt < 4; mt++) {
#pragma unroll
        for (int nt = 0; nt < 4; nt++) {
            int ch = wn + nt * 8 + cq * 2;
            int lp = wm + mt * 16 + g;                 // row m0 (local pixel)
            int i_loc = lp >> 4, j_loc = lp & 15;
            size_t ij = (size_t)(i0 + i_loc) * W + j0 + j_loc;
            size_t b0 = ((size_t)b * C + ch) * HW + ij;
            size_t b1 = b0 + HW;
            out[b0]     = fmaf(gm, acc[mt][nt][0], x[b0]);
            out[b1]     = fmaf(gm, acc[mt][nt][1], x[b1]);
            // row m1 = lp + 8 -> same i row, j + 8
            out[b0 + 8] = fmaf(gm, acc[mt][nt][2], x[b0 + 8]);
            out[b1 + 8] = fmaf(gm, acc[mt][nt][3], x[b1 + 8]);
        }
    }
}

// ---------------- launch ----------------
extern "C" void kernel_launch(void* const* d_in, const int* in_sizes, int n_in,
                              void* d_out, int out_size) {
    const float* x      = (const float*)d_in[0];
    const float* gn_w   = (const float*)d_in[1];
    const float* gn_b   = (const float*)d_in[2];
    const float* qkv_w  = (const float*)d_in[3];
    const float* proj_w = (const float*)d_in[4];
    const float* gamma  = (const float*)d_in[5];
    float* out = (float*)d_out;

    const int qkv_smem  = 2 * 128 * QST * 4;                  // 69632 B
    const int fuse_smem = (2 * 128 * QST + 2 * KSMW) * 4;     // 90496 B
    cudaFuncSetAttribute(qkv_gemm_kernel, cudaFuncAttributeMaxDynamicSharedMemorySize, qkv_smem);
    cudaFuncSetAttribute(natten_proj_kernel, cudaFuncAttributeMaxDynamicSharedMemorySize, fuse_smem);

    gn_stats_kernel<<<B * C, 256>>>(x);
    gn_finalize_kernel<<<4, 128>>>(gn_w, gn_b);
    qkv_gemm_kernel<<<(B * HW) / 128, 256, qkv_smem>>>(x, qkv_w);
    natten_proj_kernel<<<dim3(W / 16, H / 8, B), 256, fuse_smem>>>(x, proj_w, gamma, out);
}

// round 13
// speedup vs baseline: 1.4211x; 1.4211x over previous
#include <cuda_runtime.h>
#include <cuda_fp16.h>
#include <math.h>

// Problem constants (fixed shapes)
#define B 4
#define C 128
#define H 256
#define W 256
#define HW 65536
#define NH 8
#define DH 16
#define KS 7
#define GROUPS 8
#define CPG 16
#define EPS 1e-5f

// ---------------- scratch (device globals) ----------------
__device__ float    g_psum[B * C];
__device__ float    g_psum2[B * C];
__device__ float    g_scale[B * C];
__device__ float    g_shift[B * C];
// qkv packed fp16x2: [qkvi(3)][b(4)][h(8)][ij(65536)][dw(8)]
__device__ unsigned g_qkv_w[(size_t)3 * B * NH * HW * (DH / 2)];
// attn out packed fp16x2: [pix(262144)][cw(64)]
__device__ unsigned g_attn_w[(size_t)B * HW * (C / 2)];

// ---------------- helpers ----------------
__device__ __forceinline__ unsigned packh(float a, float b) {
    __half2 t = __floats2half2_rn(a, b);
    return *reinterpret_cast<unsigned*>(&t);
}
__device__ __forceinline__ void mma_f16(float* c,
                                        unsigned a0, unsigned a1, unsigned a2, unsigned a3,
                                        unsigned b0, unsigned b1) {
    asm volatile(
        "mma.sync.aligned.m16n8k16.row.col.f32.f16.f16.f32 "
        "{%0,%1,%2,%3}, {%4,%5,%6,%7}, {%8,%9}, {%0,%1,%2,%3};\n"
        : "+f"(c[0]), "+f"(c[1]), "+f"(c[2]), "+f"(c[3])
        : "r"(a0), "r"(a1), "r"(a2), "r"(a3), "r"(b0), "r"(b1));
}
// f16-accumulator MMA: D = 2 packed half2 regs; d0 = row-group 0, (col 2cq, 2cq+1)
__device__ __forceinline__ void mma_f16acc(unsigned* c,
                                           unsigned a0, unsigned a1, unsigned a2, unsigned a3,
                                           unsigned b0, unsigned b1) {
    asm volatile(
        "mma.sync.aligned.m16n8k16.row.col.f16.f16.f16.f16 "
        "{%0,%1}, {%2,%3,%4,%5}, {%6,%7}, {%0,%1};\n"
        : "+r"(c[0]), "+r"(c[1])
        : "r"(a0), "r"(a1), "r"(a2), "r"(a3), "r"(b0), "r"(b1));
}
#define EXP_SCALE 0.36067376f   // 0.25 * log2(e)
// packed logits (half2) -> scale+bias (fp16x2 fma) -> exp2. bias lane: 0 keep, 0xFC00 = -inf mask.
__device__ __forceinline__ unsigned exph2p(unsigned p, unsigned sc2, unsigned bias) {
    unsigned r;
    asm("fma.rn.f16x2 %0, %1, %2, %3;" : "=r"(r) : "r"(p), "r"(sc2), "r"(bias));
    __half2 e = h2exp2(*reinterpret_cast<__half2*>(&r));
    return *reinterpret_cast<unsigned*>(&e);
}
__device__ __forceinline__ unsigned hadd2u(unsigned a, unsigned b) {
    __half2 r = __hadd2(*reinterpret_cast<__half2*>(&a), *reinterpret_cast<__half2*>(&b));
    return *reinterpret_cast<unsigned*>(&r);
}

// ---------------- kernel 1: GN statistics ----------------
__global__ __launch_bounds__(256) void gn_stats_kernel(const float* __restrict__ x) {
    const float4* p = (const float4*)(x + (size_t)blockIdx.x * HW);
    int tid = threadIdx.x;
    float s = 0.f, s2 = 0.f;
    for (int idx = tid; idx < HW / 4; idx += 256) {
        float4 v = p[idx];
        s  += v.x + v.y + v.z + v.w;
        s2 += v.x * v.x + v.y * v.y + v.z * v.z + v.w * v.w;
    }
    __shared__ float sh[256];
    sh[tid] = s; __syncthreads();
    for (int o = 128; o > 0; o >>= 1) { if (tid < o) sh[tid] += sh[tid + o]; __syncthreads(); }
    float bs = sh[0];
    __syncthreads();
    sh[tid] = s2; __syncthreads();
    for (int o = 128; o > 0; o >>= 1) { if (tid < o) sh[tid] += sh[tid + o]; __syncthreads(); }
    if (tid == 0) { g_psum[blockIdx.x] = bs; g_psum2[blockIdx.x] = sh[0]; }
}

// ---------------- kernel 2: finalize GN scale/shift ----------------
__global__ void gn_finalize_kernel(const float* __restrict__ gn_w, const float* __restrict__ gn_b) {
    int idx = blockIdx.x * 128 + threadIdx.x;
    if (idx >= B * C) return;
    int b = idx >> 7, c = idx & 127, g = c >> 4;
    int gbase = b * C + g * CPG;
    double s = 0.0, s2 = 0.0;
#pragma unroll
    for (int t = 0; t < CPG; t++) { s += (double)g_psum[gbase + t]; s2 += (double)g_psum2[gbase + t]; }
    const double N = (double)CPG * HW;
    double mu = s / N;
    double var = s2 / N - mu * mu;
    float rstd = (float)(1.0 / sqrt(var + (double)EPS));
    float sc = rstd * gn_w[c];
    g_scale[idx] = sc;
    g_shift[idx] = gn_b[c] - (float)mu * sc;
}

// ---------------- kernel 3: QKV GEMM (f16 MMA), A staged once, 3 n-tiles in-block ----------------
#define QST 68    // smem word stride per row: 64 data words + 4 pad
extern __shared__ unsigned qsm[];   // As[128*QST] ++ Bs[128*QST] = 69632 B

__global__ __launch_bounds__(256) void qkv_gemm_kernel(const float* __restrict__ x,
                                                       const float* __restrict__ wq) {
    unsigned* As = qsm;
    unsigned* Bs = qsm + 128 * QST;

    int tid = threadIdx.x;
    int p0 = blockIdx.x * 128;
    int b  = p0 >> 16;
    int ij0 = p0 & (HW - 1);
    int warp = tid >> 5, lane = tid & 31;
    int wm = (warp >> 2) * 64, wn = (warp & 3) * 32;
    int g = lane >> 2, cq = lane & 3;

    // stage A once: 128 pixels x 64 words (128 channels), GN applied, fp16 packed
    const float* xb = x + (size_t)b * C * HW;
    int ap = tid & 127;
    int asw = (ap >> 3) & 3;
    for (int kw = tid >> 7; kw < 64; kw += 2) {
        int c = kw * 2;
        float v0 = fmaf(xb[(size_t)c * HW + ij0 + ap], g_scale[b * C + c], g_shift[b * C + c]);
        float v1 = fmaf(xb[(size_t)(c + 1) * HW + ij0 + ap], g_scale[b * C + c + 1], g_shift[b * C + c + 1]);
        As[ap * QST + (kw ^ asw)] = packh(v0, v1);
    }

    int bn = tid >> 5;
    int bkw = tid & 31;

    for (int qkvi = 0; qkvi < 3; qkvi++) {
        __syncthreads();
        for (int n = bn; n < 128; n += 8) {
            int sw = (n >> 3) & 3;
#pragma unroll
            for (int h2 = 0; h2 < 2; h2++) {
                int w = h2 * 32 + bkw;
                float2 f = *(const float2*)&wq[(size_t)(qkvi * 128 + n) * C + w * 2];
                Bs[n * QST + (w ^ sw)] = packh(f.x, f.y);
            }
        }
        __syncthreads();

        float acc[4][4][4];
#pragma unroll
        for (int mt = 0; mt < 4; mt++)
#pragma unroll
            for (int nt = 0; nt < 4; nt++)
#pragma unroll
                for (int t = 0; t < 4; t++) acc[mt][nt][t] = 0.f;

#pragma unroll
        for (int s = 0; s < 8; s++) {
            unsigned bf[4][2];
#pragma unroll
            for (int nt = 0; nt < 4; nt++) {
                int n = wn + nt * 8 + g;
                int sb = (n >> 3) & 3;
                bf[nt][0] = Bs[n * QST + ((s * 8 + cq) ^ sb)];
                bf[nt][1] = Bs[n * QST + ((s * 8 + 4 + cq) ^ sb)];
            }
#pragma unroll
            for (int mt = 0; mt < 4; mt++) {
                int m0 = wm + mt * 16 + g;
                int m1 = m0 + 8;
                int sa0 = (m0 >> 3) & 3, sa1 = (m1 >> 3) & 3;
                unsigned a0 = As[m0 * QST + ((s * 8 + cq) ^ sa0)];
                unsigned a1 = As[m1 * QST + ((s * 8 + cq) ^ sa1)];
                unsigned a2 = As[m0 * QST + ((s * 8 + 4 + cq) ^ sa0)];
                unsigned a3 = As[m1 * QST + ((s * 8 + 4 + cq) ^ sa1)];
#pragma unroll
                for (int nt = 0; nt < 4; nt++)
                    mma_f16(acc[mt][nt], a0, a1, a2, a3, bf[nt][0], bf[nt][1]);
            }
        }
        __syncthreads();

#pragma unroll
        for (int mt = 0; mt < 4; mt++) {
#pragma unroll
            for (int nt = 0; nt < 4; nt++) {
                int m0 = wm + mt * 16 + g, m1 = m0 + 8;
                int w = (wn + nt * 8) / 2 + cq;
                Bs[m0 * QST + w] = packh(acc[mt][nt][0], acc[mt][nt][1]);
                Bs[m1 * QST + w] = packh(acc[mt][nt][2], acc[mt][nt][3]);
            }
        }
        __syncthreads();

        uint4* gout = (uint4*)g_qkv_w;
        size_t tile_u4 = ((size_t)qkvi * 32 + b * 8) * ((size_t)HW * 2);
        for (int idx = tid; idx < 2048; idx += 256) {
            int h = idx >> 8;
            int rem = idx & 255;
            int ij = rem >> 1, half = rem & 1;
            uint4 val = *(uint4*)&Bs[ij * QST + h * 8 + half * 4];
            gout[tile_u4 + (size_t)h * HW * 2 + (size_t)(ij0 + ij) * 2 + half] = val;
        }
    }
}

// ---------------- kernel 4: neighborhood attention (warp-tiled tensor-core) ----------------
// block: 8i x 32j queries, 16 warps of 16 queries (2i x 8j) each; 512 threads.
// Key tile: 14 rows x 38 cols, stride 39 vectors of 8 words + 4-word row skew
// (row stride mod 32 identical to the proven 8x16 version -> same conflict-free pattern).
#define TR 14
#define TCD 38
#define TCP 39
#define VST 8
#define KSMW (TR * TCP * VST + 32)

__global__ __launch_bounds__(512) void natten_kernel() {
    __shared__ __align__(16) unsigned Ks[KSMW];
    __shared__ __align__(16) unsigned Vs[KSMW];

    int b = blockIdx.z >> 3, h = blockIdx.z & 7;
    int i0 = blockIdx.y * 8, j0 = blockIdx.x * 32;
    int rb = i0 - 3; if (rb < 0) rb = 0; if (rb > H - TR) rb = H - TR;
    int cb = j0 - 3; if (cb < 0) cb = 0; if (cb > W - TCD) cb = W - TCD;

    size_t hb = ((size_t)b * NH + h) * ((size_t)HW * 8);
    const unsigned* qg = g_qkv_w + hb;
    const unsigned* kg = qg + (size_t)(B * NH) * HW * 8;
    const unsigned* vg = kg + (size_t)(B * NH) * HW * 8;

    int tid = threadIdx.x;
    // stage K and V tiles (skewed layout)
    for (int idx = tid; idx < TR * TCD * 2; idx += 512) {
        int vec = idx >> 1, q = idx & 1;
        int r = vec / TCD, c = vec - r * TCD;
        size_t gw = ((size_t)(rb + r) * W + (cb + c)) * 8 + q * 4;
        int sw = (r * TCP + c) * VST + ((r & 7) << 2) + q * 4;
        *(uint4*)&Ks[sw] = *(const uint4*)&kg[gw];
        *(uint4*)&Vs[sw] = *(const uint4*)&vg[gw];
    }

    int warp = tid >> 5, lane = tid & 31;
    int wi = warp >> 2, wj = warp & 3;
    int qi0 = i0 + wi * 2, qj0 = j0 + wj * 8;
    int qrow = lane >> 2, qw = lane & 3;

    // Q fragment (A of QK): a0/a2 -> row group 0 (i=qi0), a1/a3 -> group 1 (i=qi0+1)
    size_t qp0 = ((size_t)qi0 * W + qj0 + qrow) * 8;
    unsigned qa0 = qg[qp0 + qw];
    unsigned qa2 = qg[qp0 + qw + 4];
    unsigned qa1 = qg[qp0 + (size_t)W * 8 + qw];
    unsigned qa3 = qg[qp0 + (size_t)W * 8 + qw + 4];

    // warp key-window bases (clamped into the tile) and residual offsets
    int si0 = qi0 - 3; if (si0 < 0) si0 = 0; if (si0 > H - 7) si0 = H - 7;
    int si1 = qi0 - 2; if (si1 < 0) si1 = 0; if (si1 > H - 7) si1 = H - 7;
    int wr0 = si0 - rb; if (wr0 > TR - 8) wr0 = TR - 8;      // keep 8-row read in-tile
    int roff = (si0 - rb) - wr0;                              // 0 or 1
    int r1 = roff + (si1 - si0);                              // 0 or 1 (group-1 row offset)
    int sj0 = qj0 - 3; if (sj0 < 0) sj0 = 0; if (sj0 > W - 7) sj0 = W - 7;
    int wc0 = sj0 - cb; if (wc0 > TCD - 14) wc0 = TCD - 14;   // keep 14-col sweep in-tile
    int oj = qj0 + qrow - 3; if (oj < 0) oj = 0; if (oj > W - 7) oj = W - 7;
    int cLo = oj - cb - wc0;                                  // valid dc in [cLo, cLo+6]

    // row-validity masks folded into fp16x2 additive biases (0 = keep, -inf = mask)
    bool v0m = (2 * qw)     >= roff;      // group0, dr=2qw
    bool v1m = (2 * qw + 1) <= roff + 6;  // group0, dr=2qw+1
    bool v2m = (2 * qw)     >= r1;        // group1, dr=2qw
    bool v3m = (2 * qw + 1) <= r1 + 6;    // group1, dr=2qw+1
    const unsigned NEG2 = 0xFC00FC00u;
    unsigned bias01 = (v0m ? 0u : 0xFC00u) | ((v1m ? 0u : 0xFC00u) << 16);
    unsigned bias23 = (v2m ? 0u : 0xFC00u) | ((v3m ? 0u : 0xFC00u) << 16);
    unsigned sc2 = packh(EXP_SCALE, EXP_SCALE);

    int kr = wr0 + qrow;
    const unsigned* kb = &Ks[(kr * TCP + wc0) * VST + ((kr & 7) << 2) + qw];
    int lm = lane & 7, mi = lane >> 3;
    int vr = wr0 + lm;
    unsigned vaddr = (unsigned)__cvta_generic_to_shared(
        &Vs[(vr * TCP + wc0 + (mi & 1)) * VST + ((vr & 7) << 2) + (mi >> 1) * 4]);

    __syncthreads();

    float o0[4] = {0.f, 0.f, 0.f, 0.f};
    float o1[4] = {0.f, 0.f, 0.f, 0.f};
    unsigned rs0 = 0u, rs1 = 0u;        // half2 row-sum partials

#pragma unroll
    for (int kc = 0; kc < 7; kc++) {
        // QK^T with f16 accumulators: D regs are packed (dr, dr+1) pairs directly
        unsigned cE[2] = {0u, 0u};
        unsigned cO[2] = {0u, 0u};
        const unsigned* ke = kb + (2 * kc) * VST;
        mma_f16acc(cE, qa0, qa1, qa2, qa3, ke[0], ke[4]);
        mma_f16acc(cO, qa0, qa1, qa2, qa3, ke[VST], ke[VST + 4]);

        // V fragments (transposed) for both d-halves
        unsigned v0, v1, v2, v3;
        asm volatile("ldmatrix.sync.aligned.m8n8.x4.trans.shared.b16 {%0,%1,%2,%3}, [%4];"
                     : "=r"(v0), "=r"(v1), "=r"(v2), "=r"(v3)
                     : "r"(vaddr + 2 * kc * VST * 4));

        bool cvE = (unsigned)(2 * kc     - cLo) <= 6u;
        bool cvO = (unsigned)(2 * kc + 1 - cLo) <= 6u;
        unsigned bE01 = cvE ? bias01 : NEG2;
        unsigned bE23 = cvE ? bias23 : NEG2;
        unsigned bO01 = cvO ? bias01 : NEG2;
        unsigned bO23 = cvO ? bias23 : NEG2;
        unsigned aE01 = exph2p(cE[0], sc2, bE01);
        unsigned aE23 = exph2p(cE[1], sc2, bE23);
        unsigned aO01 = exph2p(cO[0], sc2, bO01);
        unsigned aO23 = exph2p(cO[1], sc2, bO23);
        rs0 = hadd2u(rs0, hadd2u(aE01, aO01));
        rs1 = hadd2u(rs1, hadd2u(aE23, aO23));

        // P @ V (unnormalized, f32 accum)
        mma_f16(o0, aE01, aE23, aO01, aO23, v0, v1);
        mma_f16(o1, aE01, aE23, aO01, aO23, v2, v3);
    }

    // per-row sums: reduce across the quad (lanes xor 1, xor 2), then low+high
    rs0 = hadd2u(rs0, __shfl_xor_sync(0xffffffffu, rs0, 1));
    rs0 = hadd2u(rs0, __shfl_xor_sync(0xffffffffu, rs0, 2));
    rs1 = hadd2u(rs1, __shfl_xor_sync(0xffffffffu, rs1, 1));
    rs1 = hadd2u(rs1, __shfl_xor_sync(0xffffffffu, rs1, 2));
    __half2 r0h = *reinterpret_cast<__half2*>(&rs0);
    __half2 r1h = *reinterpret_cast<__half2*>(&rs1);
    float inv0 = 1.f / (__low2float(r0h) + __high2float(r0h));
    float inv1 = 1.f / (__low2float(r1h) + __high2float(r1h));

    size_t pix0 = (size_t)b * HW + (size_t)qi0 * W + qj0 + qrow;
    unsigned* d0 = &g_attn_w[pix0 * 64 + h * 8];
    d0[qw]     = packh(o0[0] * inv0, o0[1] * inv0);
    d0[4 + qw] = packh(o1[0] * inv0, o1[1] * inv0);
    unsigned* d1 = d0 + (size_t)64 * W;
    d1[qw]     = packh(o0[2] * inv1, o0[3] * inv1);
    d1[4 + qw] = packh(o1[2] * inv1, o1[3] * inv1);
}

// ---------------- kernel 5: proj GEMM (f16 MMA) + residual ----------------
#define SWST 36
__global__ __launch_bounds__(256) void proj_gemm_kernel(const float* __restrict__ x,
                                                        const float* __restrict__ wp,
                                                        const float* __restrict__ gamma,
                                                        float* __restrict__ out) {
    __shared__ unsigned As[128 * SWST];
    __shared__ unsigned Bs[128 * SWST];

    int tid = threadIdx.x;
    int p0 = blockIdx.x * 128;
    int b  = p0 >> 16;
    int ij0 = p0 & (HW - 1);
    int warp = tid >> 5, lane = tid & 31;
    int wm = (warp >> 2) * 64, wn = (warp & 3) * 32;
    int g = lane >> 2, cq = lane & 3;

    float acc[4][4][4];
#pragma unroll
    for (int mt = 0; mt < 4; mt++)
#pragma unroll
        for (int nt = 0; nt < 4; nt++)
#pragma unroll
            for (int t = 0; t < 4; t++) acc[mt][nt][t] = 0.f;

    int akw = tid & 31, ap0 = tid >> 5;
    int bkw = tid & 31, bn0 = tid >> 5;

    for (int stage = 0; stage < 2; stage++) {
#pragma unroll
        for (int p = ap0; p < 128; p += 8)
            As[p * SWST + (akw ^ ((p >> 3) & 3))] =
                g_attn_w[(size_t)(p0 + p) * 64 + stage * 32 + akw];
#pragma unroll
        for (int n = bn0; n < 128; n += 8) {
            float2 f = *(const float2*)&wp[(size_t)n * C + stage * 64 + bkw * 2];
            Bs[n * SWST + (bkw ^ ((n >> 3) & 3))] = packh(f.x, f.y);
        }
        __syncthreads();
#pragma unroll
        for (int s16 = 0; s16 < 4; s16++) {
            unsigned bf[4][2];
#pragma unroll
            for (int nt = 0; nt < 4; nt++) {
                int n = wn + nt * 8 + g;
                int sb = (n >> 3) & 3;
                bf[nt][0] = Bs[n * SWST + ((s16 * 8 + cq) ^ sb)];
                bf[nt][1] = Bs[n * SWST + ((s16 * 8 + 4 + cq) ^ sb)];
            }
#pragma unroll
            for (int mt = 0; mt < 4; mt++) {
                int m0 = wm + mt * 16 + g;
                int m1 = m0 + 8;
                int sa0 = (m0 >> 3) & 3, sa1 = (m1 >> 3) & 3;
                unsigned a0 = As[m0 * SWST + ((s16 * 8 + cq) ^ sa0)];
                unsigned a1 = As[m1 * SWST + ((s16 * 8 + cq) ^ sa1)];
                unsigned a2 = As[m0 * SWST + ((s16 * 8 + 4 + cq) ^ sa0)];
                unsigned a3 = As[m1 * SWST + ((s16 * 8 + 4 + cq) ^ sa1)];
#pragma unroll
                for (int nt = 0; nt < 4; nt++)
                    mma_f16(acc[mt][nt], a0, a1, a2, a3, bf[nt][0], bf[nt][1]);
            }
        }
        __syncthreads();
    }

    float gm = gamma[0];
#pragma unroll
    for (int mt = 0; mt < 4; mt++) {
#pragma unroll
        for (int nt = 0; nt < 4; nt++) {
            int ch = wn + nt * 8 + cq * 2;
            int ijl = ij0 + wm + mt * 16 + g;
            size_t b0 = ((size_t)b * C + ch) * HW + ijl;
            size_t b1 = b0 + HW;
            out[b0]     = fmaf(gm, acc[mt][nt][0], x[b0]);
            out[b1]     = fmaf(gm, acc[mt][nt][1], x[b1]);
            out[b0 + 8] = fmaf(gm, acc[mt][nt][2], x[b0 + 8]);
            out[b1 + 8] = fmaf(gm, acc[mt][nt][3], x[b1 + 8]);
        }
    }
}

// ---------------- launch ----------------
extern "C" void kernel_launch(void* const* d_in, const int* in_sizes, int n_in,
                              void* d_out, int out_size) {
    const float* x      = (const float*)d_in[0];
    const float* gn_w   = (const float*)d_in[1];
    const float* gn_b   = (const float*)d_in[2];
    const float* qkv_w  = (const float*)d_in[3];
    const float* proj_w = (const float*)d_in[4];
    const float* gamma  = (const float*)d_in[5];
    float* out = (float*)d_out;

    const int qkv_smem = 2 * 128 * QST * 4;           // 69632 B
    cudaFuncSetAttribute(qkv_gemm_kernel, cudaFuncAttributeMaxDynamicSharedMemorySize, qkv_smem);

    gn_stats_kernel<<<B * C, 256>>>(x);
    gn_finalize_kernel<<<4, 128>>>(gn_w, gn_b);
    qkv_gemm_kernel<<<(B * HW) / 128, 256, qkv_smem>>>(x, qkv_w);
    natten_kernel<<<dim3(W / 32, H / 8, B * NH), 512>>>();
    proj_gemm_kernel<<<(B * HW) / 128, 256>>>(x, proj_w, gamma, out);
}

// round 16
// speedup vs baseline: 1.5442x; 1.0867x over previous
#include <cuda_runtime.h>
#include <cuda_fp16.h>
#include <math.h>

// Problem constants (fixed shapes)
#define B 4
#define C 128
#define H 256
#define W 256
#define HW 65536
#define NH 8
#define DH 16
#define KS 7
#define GROUPS 8
#define CPG 16
#define EPS 1e-5f

// ---------------- scratch (device globals) ----------------
__device__ float    g_psum[B * C];
__device__ float    g_psum2[B * C];
__device__ float    g_scale[B * C];
__device__ float    g_shift[B * C];
// qkv packed fp16x2: [qkvi(3)][b(4)][h(8)][ij(65536)][dw(8)]
__device__ unsigned g_qkv_w[(size_t)3 * B * NH * HW * (DH / 2)];
// attn out packed fp16x2: [pix(262144)][cw(64)]
__device__ unsigned g_attn_w[(size_t)B * HW * (C / 2)];

// ---------------- helpers ----------------
__device__ __forceinline__ unsigned packh(float a, float b) {
    __half2 t = __floats2half2_rn(a, b);
    return *reinterpret_cast<unsigned*>(&t);
}
__device__ __forceinline__ void mma_f16(float* c,
                                        unsigned a0, unsigned a1, unsigned a2, unsigned a3,
                                        unsigned b0, unsigned b1) {
    asm volatile(
        "mma.sync.aligned.m16n8k16.row.col.f32.f16.f16.f32 "
        "{%0,%1,%2,%3}, {%4,%5,%6,%7}, {%8,%9}, {%0,%1,%2,%3};\n"
        : "+f"(c[0]), "+f"(c[1]), "+f"(c[2]), "+f"(c[3])
        : "r"(a0), "r"(a1), "r"(a2), "r"(a3), "r"(b0), "r"(b1));
}
// f16-accumulator MMA: D = 2 packed half2 regs; d0 = row-group 0, (col 2cq, 2cq+1)
__device__ __forceinline__ void mma_f16acc(unsigned* c,
                                           unsigned a0, unsigned a1, unsigned a2, unsigned a3,
                                           unsigned b0, unsigned b1) {
    asm volatile(
        "mma.sync.aligned.m16n8k16.row.col.f16.f16.f16.f16 "
        "{%0,%1}, {%2,%3,%4,%5}, {%6,%7}, {%0,%1};\n"
        : "+r"(c[0]), "+r"(c[1])
        : "r"(a0), "r"(a1), "r"(a2), "r"(a3), "r"(b0), "r"(b1));
}
#define EXP_SCALE 0.36067376f   // 0.25 * log2(e)
// packed logits (half2) -> scale+bias (fp16x2 fma) -> exp2. bias lane: 0 keep, 0xFC00 = -inf mask.
__device__ __forceinline__ unsigned exph2p(unsigned p, unsigned sc2, unsigned bias) {
    unsigned r;
    asm("fma.rn.f16x2 %0, %1, %2, %3;" : "=r"(r) : "r"(p), "r"(sc2), "r"(bias));
    __half2 e = h2exp2(*reinterpret_cast<__half2*>(&r));
    return *reinterpret_cast<unsigned*>(&e);
}
__device__ __forceinline__ unsigned hadd2u(unsigned a, unsigned b) {
    __half2 r = __hadd2(*reinterpret_cast<__half2*>(&a), *reinterpret_cast<__half2*>(&b));
    return *reinterpret_cast<unsigned*>(&r);
}

// ---------------- kernel 1: GN statistics ----------------
__global__ __launch_bounds__(256) void gn_stats_kernel(const float* __restrict__ x) {
    const float4* p = (const float4*)(x + (size_t)blockIdx.x * HW);
    int tid = threadIdx.x;
    float s = 0.f, s2 = 0.f;
    for (int idx = tid; idx < HW / 4; idx += 256) {
        float4 v = p[idx];
        s  += v.x + v.y + v.z + v.w;
        s2 += v.x * v.x + v.y * v.y + v.z * v.z + v.w * v.w;
    }
    __shared__ float sh[256];
    sh[tid] = s; __syncthreads();
    for (int o = 128; o > 0; o >>= 1) { if (tid < o) sh[tid] += sh[tid + o]; __syncthreads(); }
    float bs = sh[0];
    __syncthreads();
    sh[tid] = s2; __syncthreads();
    for (int o = 128; o > 0; o >>= 1) { if (tid < o) sh[tid] += sh[tid + o]; __syncthreads(); }
    if (tid == 0) { g_psum[blockIdx.x] = bs; g_psum2[blockIdx.x] = sh[0]; }
}

// ---------------- kernel 2: finalize GN scale/shift ----------------
__global__ void gn_finalize_kernel(const float* __restrict__ gn_w, const float* __restrict__ gn_b) {
    int idx = blockIdx.x * 128 + threadIdx.x;
    if (idx >= B * C) return;
    int b = idx >> 7, c = idx & 127, g = c >> 4;
    int gbase = b * C + g * CPG;
    double s = 0.0, s2 = 0.0;
#pragma unroll
    for (int t = 0; t < CPG; t++) { s += (double)g_psum[gbase + t]; s2 += (double)g_psum2[gbase + t]; }
    const double N = (double)CPG * HW;
    double mu = s / N;
    double var = s2 / N - mu * mu;
    float rstd = (float)(1.0 / sqrt(var + (double)EPS));
    float sc = rstd * gn_w[c];
    g_scale[idx] = sc;
    g_shift[idx] = gn_b[c] - (float)mu * sc;
}

// ---------------- kernel 3: QKV GEMM (f16 MMA), A staged once, 3 n-tiles in-block ----------------
#define QST 68    // smem word stride per row: 64 data words + 4 pad
extern __shared__ unsigned qsm[];   // As[128*QST] ++ Bs[128*QST] = 69632 B

__global__ __launch_bounds__(256, 3) void qkv_gemm_kernel(const float* __restrict__ x,
                                                          const float* __restrict__ wq) {
    unsigned* As = qsm;
    unsigned* Bs = qsm + 128 * QST;

    int tid = threadIdx.x;
    int p0 = blockIdx.x * 128;
    int b  = p0 >> 16;
    int ij0 = p0 & (HW - 1);
    int warp = tid >> 5, lane = tid & 31;
    int wm = (warp >> 2) * 64, wn = (warp & 3) * 32;
    int g = lane >> 2, cq = lane & 3;

    // stage A once: 128 pixels x 64 words (128 channels), GN applied, fp16 packed
    const float* xb = x + (size_t)b * C * HW;
    int ap = tid & 127;
    int asw = (ap >> 3) & 3;
    for (int kw = tid >> 7; kw < 64; kw += 2) {
        int c = kw * 2;
        float v0 = fmaf(xb[(size_t)c * HW + ij0 + ap], g_scale[b * C + c], g_shift[b * C + c]);
        float v1 = fmaf(xb[(size_t)(c + 1) * HW + ij0 + ap], g_scale[b * C + c + 1], g_shift[b * C + c + 1]);
        As[ap * QST + (kw ^ asw)] = packh(v0, v1);
    }

    int bn = tid >> 5;
    int bkw = tid & 31;

    for (int qkvi = 0; qkvi < 3; qkvi++) {
        __syncthreads();
        for (int n = bn; n < 128; n += 8) {
            int sw = (n >> 3) & 3;
#pragma unroll
            for (int h2 = 0; h2 < 2; h2++) {
                int w = h2 * 32 + bkw;
                float2 f = *(const float2*)&wq[(size_t)(qkvi * 128 + n) * C + w * 2];
                Bs[n * QST + (w ^ sw)] = packh(f.x, f.y);
            }
        }
        __syncthreads();

        float acc[4][4][4];
#pragma unroll
        for (int mt = 0; mt < 4; mt++)
#pragma unroll
            for (int nt = 0; nt < 4; nt++)
#pragma unroll
                for (int t = 0; t < 4; t++) acc[mt][nt][t] = 0.f;

#pragma unroll
        for (int s = 0; s < 8; s++) {
            unsigned bf[4][2];
#pragma unroll
            for (int nt = 0; nt < 4; nt++) {
                int n = wn + nt * 8 + g;
                int sb = (n >> 3) & 3;
                bf[nt][0] = Bs[n * QST + ((s * 8 + cq) ^ sb)];
                bf[nt][1] = Bs[n * QST + ((s * 8 + 4 + cq) ^ sb)];
            }
#pragma unroll
            for (int mt = 0; mt < 4; mt++) {
                int m0 = wm + mt * 16 + g;
                int m1 = m0 + 8;
                int sa0 = (m0 >> 3) & 3, sa1 = (m1 >> 3) & 3;
                unsigned a0 = As[m0 * QST + ((s * 8 + cq) ^ sa0)];
                unsigned a1 = As[m1 * QST + ((s * 8 + cq) ^ sa1)];
                unsigned a2 = As[m0 * QST + ((s * 8 + 4 + cq) ^ sa0)];
                unsigned a3 = As[m1 * QST + ((s * 8 + 4 + cq) ^ sa1)];
#pragma unroll
                for (int nt = 0; nt < 4; nt++)
                    mma_f16(acc[mt][nt], a0, a1, a2, a3, bf[nt][0], bf[nt][1]);
            }
        }
        __syncthreads();

#pragma unroll
        for (int mt = 0; mt < 4; mt++) {
#pragma unroll
            for (int nt = 0; nt < 4; nt++) {
                int m0 = wm + mt * 16 + g, m1 = m0 + 8;
                int w = (wn + nt * 8) / 2 + cq;
                Bs[m0 * QST + w] = packh(acc[mt][nt][0], acc[mt][nt][1]);
                Bs[m1 * QST + w] = packh(acc[mt][nt][2], acc[mt][nt][3]);
            }
        }
        __syncthreads();

        uint4* gout = (uint4*)g_qkv_w;
        size_t tile_u4 = ((size_t)qkvi * 32 + b * 8) * ((size_t)HW * 2);
        for (int idx = tid; idx < 2048; idx += 256) {
            int h = idx >> 8;
            int rem = idx & 255;
            int ij = rem >> 1, half = rem & 1;
            uint4 val = *(uint4*)&Bs[ij * QST + h * 8 + half * 4];
            gout[tile_u4 + (size_t)h * HW * 2 + (size_t)(ij0 + ij) * 2 + half] = val;
        }
    }
}

// ---------------- kernel 4: neighborhood attention (warp-tiled tensor-core) ----------------
// block: 8i x 16j queries, 8 warps of 16 queries (2i x 8j) each.
// Key tile: 14 rows x 22 cols, stride 23 vectors of 8 words + 4-word row skew
#define TR 14
#define TCD 22
#define TCP 23
#define VST 8
#define KSMW (TR * TCP * VST + 32)

__global__ __launch_bounds__(256) void natten_kernel() {
    __shared__ __align__(16) unsigned Ks[KSMW];
    __shared__ __align__(16) unsigned Vs[KSMW];

    int b = blockIdx.z >> 3, h = blockIdx.z & 7;
    int i0 = blockIdx.y * 8, j0 = blockIdx.x * 16;
    int rb = i0 - 3; if (rb < 0) rb = 0; if (rb > H - TR) rb = H - TR;
    int cb = j0 - 3; if (cb < 0) cb = 0; if (cb > W - TCD) cb = W - TCD;

    size_t hb = ((size_t)b * NH + h) * ((size_t)HW * 8);
    const unsigned* qg = g_qkv_w + hb;
    const unsigned* kg = qg + (size_t)(B * NH) * HW * 8;
    const unsigned* vg = kg + (size_t)(B * NH) * HW * 8;

    int tid = threadIdx.x;
    // stage K and V tiles (skewed layout)
    for (int idx = tid; idx < TR * TCD * 2; idx += 256) {
        int vec = idx >> 1, q = idx & 1;
        int r = vec / TCD, c = vec - r * TCD;
        size_t gw = ((size_t)(rb + r) * W + (cb + c)) * 8 + q * 4;
        int sw = (r * TCP + c) * VST + ((r & 7) << 2) + q * 4;
        *(uint4*)&Ks[sw] = *(const uint4*)&kg[gw];
        *(uint4*)&Vs[sw] = *(const uint4*)&vg[gw];
    }

    int warp = tid >> 5, lane = tid & 31;
    int wi = warp >> 1, wj = warp & 1;
    int qi0 = i0 + wi * 2, qj0 = j0 + wj * 8;
    int qrow = lane >> 2, qw = lane & 3;

    // Q fragment (A of QK): a0/a2 -> row group 0 (i=qi0), a1/a3 -> group 1 (i=qi0+1)
    size_t qp0 = ((size_t)qi0 * W + qj0 + qrow) * 8;
    unsigned qa0 = qg[qp0 + qw];
    unsigned qa2 = qg[qp0 + qw + 4];
    unsigned qa1 = qg[qp0 + (size_t)W * 8 + qw];
    unsigned qa3 = qg[qp0 + (size_t)W * 8 + qw + 4];

    // warp key-window bases (clamped into the tile) and residual offsets
    int si0 = qi0 - 3; if (si0 < 0) si0 = 0; if (si0 > H - 7) si0 = H - 7;
    int si1 = qi0 - 2; if (si1 < 0) si1 = 0; if (si1 > H - 7) si1 = H - 7;
    int wr0 = si0 - rb; if (wr0 > TR - 8) wr0 = TR - 8;      // keep 8-row read in-tile
    int roff = (si0 - rb) - wr0;                              // 0 or 1
    int r1 = roff + (si1 - si0);                              // 0 or 1 (group-1 row offset)
    int sj0 = qj0 - 3; if (sj0 < 0) sj0 = 0; if (sj0 > W - 7) sj0 = W - 7;
    int wc0 = sj0 - cb; if (wc0 > TCD - 14) wc0 = TCD - 14;   // keep 14-col sweep in-tile
    int oj = qj0 + qrow - 3; if (oj < 0) oj = 0; if (oj > W - 7) oj = W - 7;
    int cLo = oj - cb - wc0;                                  // valid dc in [cLo, cLo+6]

    // row-validity masks folded into fp16x2 additive biases (0 = keep, -inf = mask)
    bool v0m = (2 * qw)     >= roff;      // group0, dr=2qw
    bool v1m = (2 * qw + 1) <= roff + 6;  // group0, dr=2qw+1
    bool v2m = (2 * qw)     >= r1;        // group1, dr=2qw
    bool v3m = (2 * qw + 1) <= r1 + 6;    // group1, dr=2qw+1
    const unsigned NEG2 = 0xFC00FC00u;
    unsigned bias01 = (v0m ? 0u : 0xFC00u) | ((v1m ? 0u : 0xFC00u) << 16);
    unsigned bias23 = (v2m ? 0u : 0xFC00u) | ((v3m ? 0u : 0xFC00u) << 16);
    unsigned sc2 = packh(EXP_SCALE, EXP_SCALE);

    int kr = wr0 + qrow;
    const unsigned* kb = &Ks[(kr * TCP + wc0) * VST + ((kr & 7) << 2) + qw];
    int lm = lane & 7, mi = lane >> 3;
    int vr = wr0 + lm;
    unsigned vaddr = (unsigned)__cvta_generic_to_shared(
        &Vs[(vr * TCP + wc0 + (mi & 1)) * VST + ((vr & 7) << 2) + (mi >> 1) * 4]);

    __syncthreads();

    float o0[4] = {0.f, 0.f, 0.f, 0.f};
    float o1[4] = {0.f, 0.f, 0.f, 0.f};
    unsigned rs0 = 0u, rs1 = 0u;        // half2 row-sum partials

#pragma unroll
    for (int kc = 0; kc < 7; kc++) {
        // QK^T with f16 accumulators: D regs are packed (dr, dr+1) pairs directly
        unsigned cE[2] = {0u, 0u};
        unsigned cO[2] = {0u, 0u};
        const unsigned* ke = kb + (2 * kc) * VST;
        mma_f16acc(cE, qa0, qa1, qa2, qa3, ke[0], ke[4]);
        mma_f16acc(cO, qa0, qa1, qa2, qa3, ke[VST], ke[VST + 4]);

        // V fragments (transposed) for both d-halves
        unsigned v0, v1, v2, v3;
        asm volatile("ldmatrix.sync.aligned.m8n8.x4.trans.shared.b16 {%0,%1,%2,%3}, [%4];"
                     : "=r"(v0), "=r"(v1), "=r"(v2), "=r"(v3)
                     : "r"(vaddr + 2 * kc * VST * 4));

        bool cvE = (unsigned)(2 * kc     - cLo) <= 6u;
        bool cvO = (unsigned)(2 * kc + 1 - cLo) <= 6u;
        unsigned bE01 = cvE ? bias01 : NEG2;
        unsigned bE23 = cvE ? bias23 : NEG2;
        unsigned bO01 = cvO ? bias01 : NEG2;
        unsigned bO23 = cvO ? bias23 : NEG2;
        unsigned aE01 = exph2p(cE[0], sc2, bE01);
        unsigned aE23 = exph2p(cE[1], sc2, bE23);
        unsigned aO01 = exph2p(cO[0], sc2, bO01);
        unsigned aO23 = exph2p(cO[1], sc2, bO23);
        rs0 = hadd2u(rs0, hadd2u(aE01, aO01));
        rs1 = hadd2u(rs1, hadd2u(aE23, aO23));

        // P @ V (unnormalized, f32 accum)
        mma_f16(o0, aE01, aE23, aO01, aO23, v0, v1);
        mma_f16(o1, aE01, aE23, aO01, aO23, v2, v3);
    }

    // per-row sums: reduce across the quad (lanes xor 1, xor 2), then low+high
    rs0 = hadd2u(rs0, __shfl_xor_sync(0xffffffffu, rs0, 1));
    rs0 = hadd2u(rs0, __shfl_xor_sync(0xffffffffu, rs0, 2));
    rs1 = hadd2u(rs1, __shfl_xor_sync(0xffffffffu, rs1, 1));
    rs1 = hadd2u(rs1, __shfl_xor_sync(0xffffffffu, rs1, 2));
    __half2 r0h = *reinterpret_cast<__half2*>(&rs0);
    __half2 r1h = *reinterpret_cast<__half2*>(&rs1);
    float inv0 = 1.f / (__low2float(r0h) + __high2float(r0h));
    float inv1 = 1.f / (__low2float(r1h) + __high2float(r1h));

    size_t pix0 = (size_t)b * HW + (size_t)qi0 * W + qj0 + qrow;
    unsigned* d0 = &g_attn_w[pix0 * 64 + h * 8];
    d0[qw]     = packh(o0[0] * inv0, o0[1] * inv0);
    d0[4 + qw] = packh(o1[0] * inv0, o1[1] * inv0);
    unsigned* d1 = d0 + (size_t)64 * W;
    d1[qw]     = packh(o0[2] * inv1, o0[3] * inv1);
    d1[4 + qw] = packh(o1[2] * inv1, o1[3] * inv1);
}

// ---------------- kernel 5: proj GEMM (f16 MMA) + residual ----------------
#define SWST 36
__global__ __launch_bounds__(256, 3) void proj_gemm_kernel(const float* __restrict__ x,
                                                           const float* __restrict__ wp,
                                                           const float* __restrict__ gamma,
                                                           float* __restrict__ out) {
    __shared__ unsigned As[128 * SWST];
    __shared__ unsigned Bs[128 * SWST];

    int tid = threadIdx.x;
    int p0 = blockIdx.x * 128;
    int b  = p0 >> 16;
    int ij0 = p0 & (HW - 1);
    int warp = tid >> 5, lane = tid & 31;
    int wm = (warp >> 2) * 64, wn = (warp & 3) * 32;
    int g = lane >> 2, cq = lane & 3;

    float acc[4][4][4];
#pragma unroll
    for (int mt = 0; mt < 4; mt++)
#pragma unroll
        for (int nt = 0; nt < 4; nt++)
#pragma unroll
            for (int t = 0; t < 4; t++) acc[mt][nt][t] = 0.f;

    int akw = tid & 31, ap0 = tid >> 5;
    int bkw = tid & 31, bn0 = tid >> 5;

    for (int stage = 0; stage < 2; stage++) {
#pragma unroll
        for (int p = ap0; p < 128; p += 8)
            As[p * SWST + (akw ^ ((p >> 3) & 3))] =
                g_attn_w[(size_t)(p0 + p) * 64 + stage * 32 + akw];
#pragma unroll
        for (int n = bn0; n < 128; n += 8) {
            float2 f = *(const float2*)&wp[(size_t)n * C + stage * 64 + bkw * 2];
            Bs[n * SWST + (bkw ^ ((n >> 3) & 3))] = packh(f.x, f.y);
        }
        __syncthreads();
#pragma unroll
        for (int s16 = 0; s16 < 4; s16++) {
            unsigned bf[4][2];
#pragma unroll
            for (int nt = 0; nt < 4; nt++) {
                int n = wn + nt * 8 + g;
                int sb = (n >> 3) & 3;
                bf[nt][0] = Bs[n * SWST + ((s16 * 8 + cq) ^ sb)];
                bf[nt][1] = Bs[n * SWST + ((s16 * 8 + 4 + cq) ^ sb)];
            }
#pragma unroll
            for (int mt = 0; mt < 4; mt++) {
                int m0 = wm + mt * 16 + g;
                int m1 = m0 + 8;
                int sa0 = (m0 >> 3) & 3, sa1 = (m1 >> 3) & 3;
                unsigned a0 = As[m0 * SWST + ((s16 * 8 + cq) ^ sa0)];
                unsigned a1 = As[m1 * SWST + ((s16 * 8 + cq) ^ sa1)];
                unsigned a2 = As[m0 * SWST + ((s16 * 8 + 4 + cq) ^ sa0)];
                unsigned a3 = As[m1 * SWST + ((s16 * 8 + 4 + cq) ^ sa1)];
#pragma unroll
                for (int nt = 0; nt < 4; nt++)
                    mma_f16(acc[mt][nt], a0, a1, a2, a3, bf[nt][0], bf[nt][1]);
            }
        }
        __syncthreads();
    }

    float gm = gamma[0];
#pragma unroll
    for (int mt = 0; mt < 4; mt++) {
#pragma unroll
        for (int nt = 0; nt < 4; nt++) {
            int ch = wn + nt * 8 + cq * 2;
            int ijl = ij0 + wm + mt * 16 + g;
            size_t b0 = ((size_t)b * C + ch) * HW + ijl;
            size_t b1 = b0 + HW;
            out[b0]     = fmaf(gm, acc[mt][nt][0], x[b0]);
            out[b1]     = fmaf(gm, acc[mt][nt][1], x[b1]);
            out[b0 + 8] = fmaf(gm, acc[mt][nt][2], x[b0 + 8]);
            out[b1 + 8] = fmaf(gm, acc[mt][nt][3], x[b1 + 8]);
        }
    }
}

// ---------------- launch ----------------
extern "C" void kernel_launch(void* const* d_in, const int* in_sizes, int n_in,
                              void* d_out, int out_size) {
    const float* x      = (const float*)d_in[0];
    const float* gn_w   = (const float*)d_in[1];
    const float* gn_b   = (const float*)d_in[2];
    const float* qkv_w  = (const float*)d_in[3];
    const float* proj_w = (const float*)d_in[4];
    const float* gamma  = (const float*)d_in[5];
    float* out = (float*)d_out;

    const int qkv_smem = 2 * 128 * QST * 4;           // 69632 B
    cudaFuncSetAttribute(qkv_gemm_kernel, cudaFuncAttributeMaxDynamicSharedMemorySize, qkv_smem);

    gn_stats_kernel<<<B * C, 256>>>(x);
    gn_finalize_kernel<<<4, 128>>>(gn_w, gn_b);
    qkv_gemm_kernel<<<(B * HW) / 128, 256, qkv_smem>>>(x, qkv_w);
    natten_kernel<<<dim3(W / 16, H / 8, B * NH), 256>>>();
    proj_gemm_kernel<<<(B * HW) / 128, 256>>>(x, proj_w, gamma, out);
}

// round 17
// speedup vs baseline: 1.5571x; 1.0084x over previous
#include <cuda_runtime.h>
#include <cuda_fp16.h>
#include <math.h>

// Problem constants (fixed shapes)
#define B 4
#define C 128
#define H 256
#define W 256
#define HW 65536
#define NH 8
#define DH 16
#define KS 7
#define GROUPS 8
#define CPG 16
#define EPS 1e-5f

// ---------------- scratch (device globals) ----------------
__device__ float    g_psum[B * C];
__device__ float    g_psum2[B * C];
__device__ float    g_scale[B * C];
__device__ float    g_shift[B * C];
// qkv packed fp16x2: [qkvi(3)][b(4)][h(8)][ij(65536)][dw(8)]
__device__ unsigned g_qkv_w[(size_t)3 * B * NH * HW * (DH / 2)];
// attn out packed fp16x2: [pix(262144)][cw(64)]
__device__ unsigned g_attn_w[(size_t)B * HW * (C / 2)];

// ---------------- helpers ----------------
__device__ __forceinline__ unsigned packh(float a, float b) {
    __half2 t = __floats2half2_rn(a, b);
    return *reinterpret_cast<unsigned*>(&t);
}
__device__ __forceinline__ void mma_f16(float* c,
                                        unsigned a0, unsigned a1, unsigned a2, unsigned a3,
                                        unsigned b0, unsigned b1) {
    asm volatile(
        "mma.sync.aligned.m16n8k16.row.col.f32.f16.f16.f32 "
        "{%0,%1,%2,%3}, {%4,%5,%6,%7}, {%8,%9}, {%0,%1,%2,%3};\n"
        : "+f"(c[0]), "+f"(c[1]), "+f"(c[2]), "+f"(c[3])
        : "r"(a0), "r"(a1), "r"(a2), "r"(a3), "r"(b0), "r"(b1));
}
// f16-accumulator MMA: D = 2 packed half2 regs; d0 = row-group 0, (col 2cq, 2cq+1)
__device__ __forceinline__ void mma_f16acc(unsigned* c,
                                           unsigned a0, unsigned a1, unsigned a2, unsigned a3,
                                           unsigned b0, unsigned b1) {
    asm volatile(
        "mma.sync.aligned.m16n8k16.row.col.f16.f16.f16.f16 "
        "{%0,%1}, {%2,%3,%4,%5}, {%6,%7}, {%0,%1};\n"
        : "+r"(c[0]), "+r"(c[1])
        : "r"(a0), "r"(a1), "r"(a2), "r"(a3), "r"(b0), "r"(b1));
}
#define EXP_SCALE 0.36067376f   // 0.25 * log2(e)
// packed logits (half2) -> scale+bias (fp16x2 fma) -> exp2. bias lane: 0 keep, 0xFC00 = -inf mask.
__device__ __forceinline__ unsigned exph2p(unsigned p, unsigned sc2, unsigned bias) {
    unsigned r;
    asm("fma.rn.f16x2 %0, %1, %2, %3;" : "=r"(r) : "r"(p), "r"(sc2), "r"(bias));
    __half2 e = h2exp2(*reinterpret_cast<__half2*>(&r));
    return *reinterpret_cast<unsigned*>(&e);
}

// ---------------- kernel 1: GN statistics ----------------
__global__ __launch_bounds__(256) void gn_stats_kernel(const float* __restrict__ x) {
    const float4* p = (const float4*)(x + (size_t)blockIdx.x * HW);
    int tid = threadIdx.x;
    float s = 0.f, s2 = 0.f;
    for (int idx = tid; idx < HW / 4; idx += 256) {
        float4 v = p[idx];
        s  += v.x + v.y + v.z + v.w;
        s2 += v.x * v.x + v.y * v.y + v.z * v.z + v.w * v.w;
    }
    __shared__ float sh[256];
    sh[tid] = s; __syncthreads();
    for (int o = 128; o > 0; o >>= 1) { if (tid < o) sh[tid] += sh[tid + o]; __syncthreads(); }
    float bs = sh[0];
    __syncthreads();
    sh[tid] = s2; __syncthreads();
    for (int o = 128; o > 0; o >>= 1) { if (tid < o) sh[tid] += sh[tid + o]; __syncthreads(); }
    if (tid == 0) { g_psum[blockIdx.x] = bs; g_psum2[blockIdx.x] = sh[0]; }
}

// ---------------- kernel 2: finalize GN scale/shift ----------------
__global__ void gn_finalize_kernel(const float* __restrict__ gn_w, const float* __restrict__ gn_b) {
    int idx = blockIdx.x * 128 + threadIdx.x;
    if (idx >= B * C) return;
    int b = idx >> 7, c = idx & 127, g = c >> 4;
    int gbase = b * C + g * CPG;
    double s = 0.0, s2 = 0.0;
#pragma unroll
    for (int t = 0; t < CPG; t++) { s += (double)g_psum[gbase + t]; s2 += (double)g_psum2[gbase + t]; }
    const double N = (double)CPG * HW;
    double mu = s / N;
    double var = s2 / N - mu * mu;
    float rstd = (float)(1.0 / sqrt(var + (double)EPS));
    float sc = rstd * gn_w[c];
    g_scale[idx] = sc;
    g_shift[idx] = gn_b[c] - (float)mu * sc;
}

// ---------------- kernel 3: QKV GEMM (f16 MMA), A staged once, 3 n-tiles in-block ----------------
#define QST 68    // smem word stride per row: 64 data words + 4 pad
extern __shared__ unsigned qsm[];   // As[128*QST] ++ Bs[128*QST] = 69632 B

__global__ __launch_bounds__(256, 3) void qkv_gemm_kernel(const float* __restrict__ x,
                                                          const float* __restrict__ wq) {
    unsigned* As = qsm;
    unsigned* Bs = qsm + 128 * QST;

    int tid = threadIdx.x;
    int p0 = blockIdx.x * 128;
    int b  = p0 >> 16;
    int ij0 = p0 & (HW - 1);
    int warp = tid >> 5, lane = tid & 31;
    int wm = (warp >> 2) * 64, wn = (warp & 3) * 32;
    int g = lane >> 2, cq = lane & 3;

    // stage A once: 128 pixels x 64 words (128 channels), GN applied, fp16 packed
    const float* xb = x + (size_t)b * C * HW;
    int ap = tid & 127;
    int asw = (ap >> 3) & 3;
    for (int kw = tid >> 7; kw < 64; kw += 2) {
        int c = kw * 2;
        float v0 = fmaf(xb[(size_t)c * HW + ij0 + ap], g_scale[b * C + c], g_shift[b * C + c]);
        float v1 = fmaf(xb[(size_t)(c + 1) * HW + ij0 + ap], g_scale[b * C + c + 1], g_shift[b * C + c + 1]);
        As[ap * QST + (kw ^ asw)] = packh(v0, v1);
    }

    int bn = tid >> 5;
    int bkw = tid & 31;

    for (int qkvi = 0; qkvi < 3; qkvi++) {
        __syncthreads();
        for (int n = bn; n < 128; n += 8) {
            int sw = (n >> 3) & 3;
#pragma unroll
            for (int h2 = 0; h2 < 2; h2++) {
                int w = h2 * 32 + bkw;
                float2 f = *(const float2*)&wq[(size_t)(qkvi * 128 + n) * C + w * 2];
                Bs[n * QST + (w ^ sw)] = packh(f.x, f.y);
            }
        }
        __syncthreads();

        float acc[4][4][4];
#pragma unroll
        for (int mt = 0; mt < 4; mt++)
#pragma unroll
            for (int nt = 0; nt < 4; nt++)
#pragma unroll
                for (int t = 0; t < 4; t++) acc[mt][nt][t] = 0.f;

#pragma unroll
        for (int s = 0; s < 8; s++) {
            unsigned bf[4][2];
#pragma unroll
            for (int nt = 0; nt < 4; nt++) {
                int n = wn + nt * 8 + g;
                int sb = (n >> 3) & 3;
                bf[nt][0] = Bs[n * QST + ((s * 8 + cq) ^ sb)];
                bf[nt][1] = Bs[n * QST + ((s * 8 + 4 + cq) ^ sb)];
            }
#pragma unroll
            for (int mt = 0; mt < 4; mt++) {
                int m0 = wm + mt * 16 + g;
                int m1 = m0 + 8;
                int sa0 = (m0 >> 3) & 3, sa1 = (m1 >> 3) & 3;
                unsigned a0 = As[m0 * QST + ((s * 8 + cq) ^ sa0)];
                unsigned a1 = As[m1 * QST + ((s * 8 + cq) ^ sa1)];
                unsigned a2 = As[m0 * QST + ((s * 8 + 4 + cq) ^ sa0)];
                unsigned a3 = As[m1 * QST + ((s * 8 + 4 + cq) ^ sa1)];
#pragma unroll
                for (int nt = 0; nt < 4; nt++)
                    mma_f16(acc[mt][nt], a0, a1, a2, a3, bf[nt][0], bf[nt][1]);
            }
        }
        __syncthreads();

#pragma unroll
        for (int mt = 0; mt < 4; mt++) {
#pragma unroll
            for (int nt = 0; nt < 4; nt++) {
                int m0 = wm + mt * 16 + g, m1 = m0 + 8;
                int w = (wn + nt * 8) / 2 + cq;
                Bs[m0 * QST + w] = packh(acc[mt][nt][0], acc[mt][nt][1]);
                Bs[m1 * QST + w] = packh(acc[mt][nt][2], acc[mt][nt][3]);
            }
        }
        __syncthreads();

        uint4* gout = (uint4*)g_qkv_w;
        size_t tile_u4 = ((size_t)qkvi * 32 + b * 8) * ((size_t)HW * 2);
        for (int idx = tid; idx < 2048; idx += 256) {
            int h = idx >> 8;
            int rem = idx & 255;
            int ij = rem >> 1, half = rem & 1;
            uint4 val = *(uint4*)&Bs[ij * QST + h * 8 + half * 4];
            gout[tile_u4 + (size_t)h * HW * 2 + (size_t)(ij0 + ij) * 2 + half] = val;
        }
    }
}

// ---------------- kernel 4: neighborhood attention (warp-tiled tensor-core) ----------------
// block: 8i x 16j queries, 8 warps of 16 queries (2i x 8j) each.
// Key tile: 14 rows x 22 cols, stride 23 vectors of 8 words + 4-word row skew
#define TR 14
#define TCD 22
#define TCP 23
#define VST 8
#define KSMW (TR * TCP * VST + 32)

__global__ __launch_bounds__(256) void natten_kernel() {
    __shared__ __align__(16) unsigned Ks[KSMW];
    __shared__ __align__(16) unsigned Vs[KSMW];

    int b = blockIdx.z >> 3, h = blockIdx.z & 7;
    int i0 = blockIdx.y * 8, j0 = blockIdx.x * 16;
    int rb = i0 - 3; if (rb < 0) rb = 0; if (rb > H - TR) rb = H - TR;
    int cb = j0 - 3; if (cb < 0) cb = 0; if (cb > W - TCD) cb = W - TCD;

    size_t hb = ((size_t)b * NH + h) * ((size_t)HW * 8);
    const unsigned* qg = g_qkv_w + hb;
    const unsigned* kg = qg + (size_t)(B * NH) * HW * 8;
    const unsigned* vg = kg + (size_t)(B * NH) * HW * 8;

    int tid = threadIdx.x;
    // stage K and V tiles (skewed layout)
    for (int idx = tid; idx < TR * TCD * 2; idx += 256) {
        int vec = idx >> 1, q = idx & 1;
        int r = vec / TCD, c = vec - r * TCD;
        size_t gw = ((size_t)(rb + r) * W + (cb + c)) * 8 + q * 4;
        int sw = (r * TCP + c) * VST + ((r & 7) << 2) + q * 4;
        *(uint4*)&Ks[sw] = *(const uint4*)&kg[gw];
        *(uint4*)&Vs[sw] = *(const uint4*)&vg[gw];
    }

    int warp = tid >> 5, lane = tid & 31;
    int wi = warp >> 1, wj = warp & 1;
    int qi0 = i0 + wi * 2, qj0 = j0 + wj * 8;
    int qrow = lane >> 2, qw = lane & 3;

    // Q fragment (A of QK): a0/a2 -> row group 0 (i=qi0), a1/a3 -> group 1 (i=qi0+1)
    size_t qp0 = ((size_t)qi0 * W + qj0 + qrow) * 8;
    unsigned qa0 = qg[qp0 + qw];
    unsigned qa2 = qg[qp0 + qw + 4];
    unsigned qa1 = qg[qp0 + (size_t)W * 8 + qw];
    unsigned qa3 = qg[qp0 + (size_t)W * 8 + qw + 4];

    // warp key-window bases (clamped into the tile) and residual offsets
    int si0 = qi0 - 3; if (si0 < 0) si0 = 0; if (si0 > H - 7) si0 = H - 7;
    int si1 = qi0 - 2; if (si1 < 0) si1 = 0; if (si1 > H - 7) si1 = H - 7;
    int wr0 = si0 - rb; if (wr0 > TR - 8) wr0 = TR - 8;      // keep 8-row read in-tile
    int roff = (si0 - rb) - wr0;                              // 0 or 1
    int r1 = roff + (si1 - si0);                              // 0 or 1 (group-1 row offset)
    int sj0 = qj0 - 3; if (sj0 < 0) sj0 = 0; if (sj0 > W - 7) sj0 = W - 7;
    int wc0 = sj0 - cb; if (wc0 > TCD - 14) wc0 = TCD - 14;   // keep 14-col sweep in-tile
    int oj = qj0 + qrow - 3; if (oj < 0) oj = 0; if (oj > W - 7) oj = W - 7;
    int cLo = oj - cb - wc0;                                  // valid dc in [cLo, cLo+6]

    // row-validity masks folded into fp16x2 additive biases (0 = keep, -inf = mask)
    bool v0m = (2 * qw)     >= roff;      // group0, dr=2qw
    bool v1m = (2 * qw + 1) <= roff + 6;  // group0, dr=2qw+1
    bool v2m = (2 * qw)     >= r1;        // group1, dr=2qw
    bool v3m = (2 * qw + 1) <= r1 + 6;    // group1, dr=2qw+1
    const unsigned NEG2 = 0xFC00FC00u;
    const unsigned ONES2 = 0x3C003C00u;   // fp16x2 (1.0, 1.0)
    unsigned bias01 = (v0m ? 0u : 0xFC00u) | ((v1m ? 0u : 0xFC00u) << 16);
    unsigned bias23 = (v2m ? 0u : 0xFC00u) | ((v3m ? 0u : 0xFC00u) << 16);
    unsigned sc2 = packh(EXP_SCALE, EXP_SCALE);

    int kr = wr0 + qrow;
    const unsigned* kb = &Ks[(kr * TCP + wc0) * VST + ((kr & 7) << 2) + qw];
    int lm = lane & 7, mi = lane >> 3;
    int vr = wr0 + lm;
    unsigned vaddr = (unsigned)__cvta_generic_to_shared(
        &Vs[(vr * TCP + wc0 + (mi & 1)) * VST + ((vr & 7) << 2) + (mi >> 1) * 4]);

    __syncthreads();

    float o0[4] = {0.f, 0.f, 0.f, 0.f};
    float o1[4] = {0.f, 0.f, 0.f, 0.f};
    float rsum[4] = {0.f, 0.f, 0.f, 0.f};   // row sums via ones-MMA (quad-reduced)

#pragma unroll
    for (int kc = 0; kc < 7; kc++) {
        // QK^T with f16 accumulators: D regs are packed (dr, dr+1) pairs directly
        unsigned cE[2] = {0u, 0u};
        unsigned cO[2] = {0u, 0u};
        const unsigned* ke = kb + (2 * kc) * VST;
        mma_f16acc(cE, qa0, qa1, qa2, qa3, ke[0], ke[4]);
        mma_f16acc(cO, qa0, qa1, qa2, qa3, ke[VST], ke[VST + 4]);

        // V fragments (transposed) for both d-halves
        unsigned v0, v1, v2, v3;
        asm volatile("ldmatrix.sync.aligned.m8n8.x4.trans.shared.b16 {%0,%1,%2,%3}, [%4];"
                     : "=r"(v0), "=r"(v1), "=r"(v2), "=r"(v3)
                     : "r"(vaddr + 2 * kc * VST * 4));

        bool cvE = (unsigned)(2 * kc     - cLo) <= 6u;
        bool cvO = (unsigned)(2 * kc + 1 - cLo) <= 6u;
        unsigned bE01 = cvE ? bias01 : NEG2;
        unsigned bE23 = cvE ? bias23 : NEG2;
        unsigned bO01 = cvO ? bias01 : NEG2;
        unsigned bO23 = cvO ? bias23 : NEG2;
        unsigned aE01 = exph2p(cE[0], sc2, bE01);
        unsigned aE23 = exph2p(cE[1], sc2, bE23);
        unsigned aO01 = exph2p(cO[0], sc2, bO01);
        unsigned aO23 = exph2p(cO[1], sc2, bO23);

        // P @ V (unnormalized, f32 accum) + row sums via all-ones B fragment
        mma_f16(o0, aE01, aE23, aO01, aO23, v0, v1);
        mma_f16(o1, aE01, aE23, aO01, aO23, v2, v3);
        mma_f16(rsum, aE01, aE23, aO01, aO23, ONES2, ONES2);
    }

    // rsum[0] = group-0 row sum, rsum[2] = group-1 row sum (MMA quad-reduced; no shuffles)
    float inv0 = 1.f / rsum[0];
    float inv1 = 1.f / rsum[2];

    size_t pix0 = (size_t)b * HW + (size_t)qi0 * W + qj0 + qrow;
    unsigned* d0 = &g_attn_w[pix0 * 64 + h * 8];
    d0[qw]     = packh(o0[0] * inv0, o0[1] * inv0);
    d0[4 + qw] = packh(o1[0] * inv0, o1[1] * inv0);
    unsigned* d1 = d0 + (size_t)64 * W;
    d1[qw]     = packh(o0[2] * inv1, o0[3] * inv1);
    d1[4 + qw] = packh(o1[2] * inv1, o1[3] * inv1);
}

// ---------------- kernel 5: proj GEMM (f16 MMA) + residual ----------------
#define SWST 36
__global__ __launch_bounds__(256, 3) void proj_gemm_kernel(const float* __restrict__ x,
                                                           const float* __restrict__ wp,
                                                           const float* __restrict__ gamma,
                                                           float* __restrict__ out) {
    __shared__ unsigned As[128 * SWST];
    __shared__ unsigned Bs[128 * SWST];

    int tid = threadIdx.x;
    int p0 = blockIdx.x * 128;
    int b  = p0 >> 16;
    int ij0 = p0 & (HW - 1);
    int warp = tid >> 5, lane = tid & 31;
    int wm = (warp >> 2) * 64, wn = (warp & 3) * 32;
    int g = lane >> 2, cq = lane & 3;

    float acc[4][4][4];
#pragma unroll
    for (int mt = 0; mt < 4; mt++)
#pragma unroll
        for (int nt = 0; nt < 4; nt++)
#pragma unroll
            for (int t = 0; t < 4; t++) acc[mt][nt][t] = 0.f;

    int akw = tid & 31, ap0 = tid >> 5;
    int bkw = tid & 31, bn0 = tid >> 5;

    for (int stage = 0; stage < 2; stage++) {
#pragma unroll
        for (int p = ap0; p < 128; p += 8)
            As[p * SWST + (akw ^ ((p >> 3) & 3))] =
                g_attn_w[(size_t)(p0 + p) * 64 + stage * 32 + akw];
#pragma unroll
        for (int n = bn0; n < 128; n += 8) {
            float2 f = *(const float2*)&wp[(size_t)n * C + stage * 64 + bkw * 2];
            Bs[n * SWST + (bkw ^ ((n >> 3) & 3))] = packh(f.x, f.y);
        }
        __syncthreads();
#pragma unroll
        for (int s16 = 0; s16 < 4; s16++) {
            unsigned bf[4][2];
#pragma unroll
            for (int nt = 0; nt < 4; nt++) {
                int n = wn + nt * 8 + g;
                int sb = (n >> 3) & 3;
                bf[nt][0] = Bs[n * SWST + ((s16 * 8 + cq) ^ sb)];
                bf[nt][1] = Bs[n * SWST + ((s16 * 8 + 4 + cq) ^ sb)];
            }
#pragma unroll
            for (int mt = 0; mt < 4; mt++) {
                int m0 = wm + mt * 16 + g;
                int m1 = m0 + 8;
                int sa0 = (m0 >> 3) & 3, sa1 = (m1 >> 3) & 3;
                unsigned a0 = As[m0 * SWST + ((s16 * 8 + cq) ^ sa0)];
                unsigned a1 = As[m1 * SWST + ((s16 * 8 + cq) ^ sa1)];
                unsigned a2 = As[m0 * SWST + ((s16 * 8 + 4 + cq) ^ sa0)];
                unsigned a3 = As[m1 * SWST + ((s16 * 8 + 4 + cq) ^ sa1)];
#pragma unroll
                for (int nt = 0; nt < 4; nt++)
                    mma_f16(acc[mt][nt], a0, a1, a2, a3, bf[nt][0], bf[nt][1]);
            }
        }
        __syncthreads();
    }

    float gm = gamma[0];
#pragma unroll
    for (int mt = 0; mt < 4; mt++) {
#pragma unroll
        for (int nt = 0; nt < 4; nt++) {
            int ch = wn + nt * 8 + cq * 2;
            int ijl = ij0 + wm + mt * 16 + g;
            size_t b0 = ((size_t)b * C + ch) * HW + ijl;
            size_t b1 = b0 + HW;
            out[b0]     = fmaf(gm, acc[mt][nt][0], x[b0]);
            out[b1]     = fmaf(gm, acc[mt][nt][1], x[b1]);
            out[b0 + 8] = fmaf(gm, acc[mt][nt][2], x[b0 + 8]);
            out[b1 + 8] = fmaf(gm, acc[mt][nt][3], x[b1 + 8]);
        }
    }
}

// ---------------- launch ----------------
extern "C" void kernel_launch(void* const* d_in, const int* in_sizes, int n_in,
                              void* d_out, int out_size) {
    const float* x      = (const float*)d_in[0];
    const float* gn_w   = (const float*)d_in[1];
    const float* gn_b   = (const float*)d_in[2];
    const float* qkv_w  = (const float*)d_in[3];
    const float* proj_w = (const float*)d_in[4];
    const float* gamma  = (const float*)d_in[5];
    float* out = (float*)d_out;

    const int qkv_smem = 2 * 128 * QST * 4;           // 69632 B
    cudaFuncSetAttribute(qkv_gemm_kernel, cudaFuncAttributeMaxDynamicSharedMemorySize, qkv_smem);

    gn_stats_kernel<<<B * C, 256>>>(x);
    gn_finalize_kernel<<<4, 128>>>(gn_w, gn_b);
    qkv_gemm_kernel<<<(B * HW) / 128, 256, qkv_smem>>>(x, qkv_w);
    natten_kernel<<<dim3(W / 16, H / 8, B * NH), 256>>>();
    proj_gemm_kernel<<<(B * HW) / 128, 256>>>(x, proj_w, gamma, out);
}